// round 5
// baseline (speedup 1.0000x reference)
#include <cuda_runtime.h>
#include <cstdint>

#define BATCH 256
#define L 4096
#define H 128

// ---------- packed f32x2 helpers (Blackwell sm_103a) ----------
__device__ __forceinline__ uint64_t pack2f(float a, float b) {
    uint64_t r; asm("mov.b64 %0, {%1, %2};" : "=l"(r) : "f"(a), "f"(b)); return r;
}
__device__ __forceinline__ float hsum2(uint64_t v) {
    float a, b; asm("mov.b64 {%0, %1}, %2;" : "=f"(a), "=f"(b) : "l"(v)); return a + b;
}
__device__ __forceinline__ uint64_t ffma2(uint64_t a, uint64_t b, uint64_t c) {
    uint64_t d; asm("fma.rn.f32x2 %0, %1, %2, %3;" : "=l"(d) : "l"(a), "l"(b), "l"(c)); return d;
}
__device__ __forceinline__ uint64_t fadd2(uint64_t a, uint64_t b) {
    uint64_t d; asm("add.rn.f32x2 %0, %1, %2;" : "=l"(d) : "l"(a), "l"(b)); return d;
}
// branchless elu
__device__ __forceinline__ float elu1(float x) {
    return fmaxf(x, 0.f) + (__expf(fminf(x, 0.f)) - 1.f);
}

// Named barriers: FWD (id 1): A arrives, B syncs (h1(t) ready + B-internal).
//                 BWD (id 2): B arrives, A syncs (pacing + A-internal).
#define BAR_SYNC_FWD()   asm volatile("bar.sync 1, 256;"   ::: "memory")
#define BAR_ARRIVE_FWD() asm volatile("bar.arrive 1, 256;" ::: "memory")
#define BAR_SYNC_BWD()   asm volatile("bar.sync 2, 256;"   ::: "memory")
#define BAR_ARRIVE_BWD() asm volatile("bar.arrive 2, 256;" ::: "memory")

// Amortized output head: reduce `cnt` ring slots starting at u0 for batch b.
__device__ __forceinline__ float head_reduce(int u0, int cnt, int b, int lane,
                                             const float (*sh_prod)[2 * H],
                                             const uint8_t* sh_x, float bout)
{
    float add = 0.f;
    for (int e = 0; e < cnt; ++e) {
        const int u = u0 + e;
        const float4 v = *(const float4*)&sh_prod[u & 31][b * H + lane * 4];
        float s = (v.x + v.y) + (v.z + v.w);
        #pragma unroll
        for (int off = 16; off; off >>= 1)
            s += __shfl_xor_sync(0xffffffffu, s, off);
        if (lane == 0) {
            const float logit = s + bout;
            const int   xt    = sh_x[b * L + u];
            const float m     = fmaxf(logit, 0.f);
            const float lse   = m + __logf(__expf(-m) + __expf(logit - m));
            add += 0.5f * ((xt ? logit : 0.f) - lse);
        }
    }
    return add;
}

// One CTA = 2 batch elements, 256 threads.
// Group A (warps 0-3, 128 threads): layer-1 recurrence for both batches.
//   Thread i holds W_c[0][:,i] (64 packed regs); full 128-dot per batch, no shfl.
// Group B (warps 4-7): layer-2 recurrence + output products, same structure.
// A runs one step ahead of B (BWD barrier primed once). No __syncthreads in loop.
__global__ void __launch_bounds__(256, 1)
rnn_scan_kernel(const int* __restrict__ x,
                const float* __restrict__ W_in,
                const float* __restrict__ W_c,
                const float* __restrict__ W_out,
                const float* __restrict__ b_out,
                float* __restrict__ out)
{
    __shared__ __align__(16) float sh_h1[2][2 * H];   // written by A; read A(t-1), B(t)
    __shared__ __align__(16) float sh_h2[2][2 * H];   // B-private ping-pong
    __shared__ float sh_r[3 * H];                     // r for spin0, spin1, zero-prev
    __shared__ __align__(16) float sh_prod[32][2 * H];// 32 KB ring of h2*wout
    __shared__ uint8_t sh_x[2 * L];                   // x as bytes (8 KB)
    __shared__ float sh_acc[8];

    const int tid  = threadIdx.x;
    const int warp = tid >> 5;
    const int lane = tid & 31;
    const int i    = tid & 127;          // output unit within group
    const int b0   = blockIdx.x * 2;

    // ---- stage x; precompute r; zero initial state ----
    const int* xg = x + (size_t)b0 * L;
    #pragma unroll 4
    for (int idx = tid; idx < 2 * L; idx += 256) sh_x[idx] = (uint8_t)xg[idx];
    if (tid < 2 * H) sh_r[tid] = elu1(W_in[tid]);
    if (tid < H)     sh_r[2 * H + tid] = 0.f;
    if (tid < 2 * H) { sh_h1[0][tid] = 0.f; sh_h2[0][tid] = 0.f; }

    const float bout = b_out[0];
    float acc = 0.f;
    __syncthreads();

    if (warp < 4) {
        // ================= GROUP A: layer 1 =================
        uint64_t wp[64];
        #pragma unroll
        for (int j = 0; j < 64; ++j)
            wp[j] = pack2f(W_c[(2 * j) * H + i], W_c[(2 * j + 1) * H + i]);

        for (int t = 0; t < L; ++t) {
            BAR_SYNC_BWD();                 // primed: pairs with B(t-1)'s arrive
            const int p = t & 1;
            const float* h1r = &sh_h1[p][0];
            const int prev0 = t ? (int)sh_x[t - 1]     : 2;
            const int prev1 = t ? (int)sh_x[L + t - 1] : 2;
            const float rv0 = sh_r[prev0 * H + i];
            const float rv1 = sh_r[prev1 * H + i];

            uint64_t a0 = 0, a1 = 0, a2 = 0, a3 = 0;
            uint64_t c0 = 0, c1 = 0, c2 = 0, c3 = 0;
            #pragma unroll
            for (int m = 0; m < 16; ++m) {
                const ulonglong2 u0 = *(const ulonglong2*)(h1r + 8 * m);
                const ulonglong2 u1 = *(const ulonglong2*)(h1r + 8 * m + 4);
                const ulonglong2 v0 = *(const ulonglong2*)(h1r + H + 8 * m);
                const ulonglong2 v1 = *(const ulonglong2*)(h1r + H + 8 * m + 4);
                a0 = ffma2(wp[4*m],   u0.x, a0);
                a1 = ffma2(wp[4*m+1], u0.y, a1);
                a2 = ffma2(wp[4*m+2], u1.x, a2);
                a3 = ffma2(wp[4*m+3], u1.y, a3);
                c0 = ffma2(wp[4*m],   v0.x, c0);
                c1 = ffma2(wp[4*m+1], v0.y, c1);
                c2 = ffma2(wp[4*m+2], v1.x, c2);
                c3 = ffma2(wp[4*m+3], v1.y, c3);
            }
            const float d0 = hsum2(fadd2(fadd2(a0, a1), fadd2(a2, a3)));
            const float d1 = hsum2(fadd2(fadd2(c0, c1), fadd2(c2, c3)));
            const float h1n0 = elu1(d0) + rv0;
            const float h1n1 = elu1(d1) + rv1;
            sh_h1[p ^ 1][i]     = h1n0;
            sh_h1[p ^ 1][H + i] = h1n1;

            // head for batch 0 BEFORE the FWD arrive (keeps ring reads ahead of
            // B(t)'s write to slot t&31, which only starts after our arrive)
            if ((t & 15) == 0 && t >= 32)
                acc += head_reduce(t - 32 + 4 * warp, 4, 0, lane, sh_prod, sh_x, bout);

            BAR_ARRIVE_FWD();
        }
    } else {
        // ================= GROUP B: layer 2 + output head =================
        const float* Wc1 = W_c + H * H;
        uint64_t wp[64];
        #pragma unroll
        for (int j = 0; j < 64; ++j)
            wp[j] = pack2f(Wc1[(2 * j) * H + i], Wc1[(2 * j + 1) * H + i]);
        const float wout_i = W_out[i];

        BAR_ARRIVE_BWD();                   // prime: lets A run 1 step ahead

        for (int t = 0; t < L; ++t) {
            BAR_SYNC_FWD();                 // h1(t) ready + B-internal barrier
            BAR_ARRIVE_BWD();               // immediately release A (slot-safe)
            const int p = t & 1;
            const float* h2r = &sh_h2[p][0];
            const float h1n0 = sh_h1[p ^ 1][i];       // h1(t)
            const float h1n1 = sh_h1[p ^ 1][H + i];

            uint64_t a0 = 0, a1 = 0, a2 = 0, a3 = 0;
            uint64_t c0 = 0, c1 = 0, c2 = 0, c3 = 0;
            #pragma unroll
            for (int m = 0; m < 16; ++m) {
                const ulonglong2 u0 = *(const ulonglong2*)(h2r + 8 * m);
                const ulonglong2 u1 = *(const ulonglong2*)(h2r + 8 * m + 4);
                const ulonglong2 v0 = *(const ulonglong2*)(h2r + H + 8 * m);
                const ulonglong2 v1 = *(const ulonglong2*)(h2r + H + 8 * m + 4);
                a0 = ffma2(wp[4*m],   u0.x, a0);
                a1 = ffma2(wp[4*m+1], u0.y, a1);
                a2 = ffma2(wp[4*m+2], u1.x, a2);
                a3 = ffma2(wp[4*m+3], u1.y, a3);
                c0 = ffma2(wp[4*m],   v0.x, c0);
                c1 = ffma2(wp[4*m+1], v0.y, c1);
                c2 = ffma2(wp[4*m+2], v1.x, c2);
                c3 = ffma2(wp[4*m+3], v1.y, c3);
            }
            const float d0 = hsum2(fadd2(fadd2(a0, a1), fadd2(a2, a3)));
            const float d1 = hsum2(fadd2(fadd2(c0, c1), fadd2(c2, c3)));
            const float h2n0 = elu1(d0) + h1n0;
            const float h2n1 = elu1(d1) + h1n1;
            sh_h2[p ^ 1][i]     = h2n0;
            sh_h2[p ^ 1][H + i] = h2n1;
            sh_prod[t & 31][i]     = h2n0 * wout_i;
            sh_prod[t & 31][H + i] = h2n1 * wout_i;

            // head for batch 1 (B's own ring writes; internally ordered)
            if ((t & 15) == 0 && t >= 32)
                acc += head_reduce(t - 32 + 4 * (warp - 4), 4, 1, lane, sh_prod, sh_x, bout);
        }
    }

    __syncthreads();

    // ---- epilogue: last 32 slots [L-32, L-1]; 8 per warp ----
    acc += head_reduce(L - 32 + 8 * (warp & 3), 8, warp >> 2, lane, sh_prod, sh_x, bout);

    if (lane == 0) sh_acc[warp] = acc;
    __syncthreads();
    if (tid < 2) {
        out[b0 + tid] = sh_acc[4 * tid] + sh_acc[4 * tid + 1]
                      + sh_acc[4 * tid + 2] + sh_acc[4 * tid + 3];
    }
}

extern "C" void kernel_launch(void* const* d_in, const int* in_sizes, int n_in,
                              void* d_out, int out_size)
{
    const int*   x     = (const int*)  d_in[0];
    const float* W_in  = (const float*)d_in[1];
    const float* W_c   = (const float*)d_in[2];
    const float* W_out = (const float*)d_in[3];
    const float* b_out = (const float*)d_in[4];

    rnn_scan_kernel<<<BATCH / 2, 256>>>(x, W_in, W_c, W_out, b_out, (float*)d_out);
}